// round 15
// baseline (speedup 1.0000x reference)
#include <cuda_runtime.h>
#include <cuda_fp16.h>
#include <stdint.h>

// LSTM B=128,T=256,H=1024,C=10 — persistent mma.sync kernel.
// R15 = R11 (single-pass fp16, KC=128, warp-spec producer, NBUF=3) with the
// monolithic grid barrier replaced by per-chunk DATAFLOW polling in the
// producer warp: chunk ch of h(t-1) is produced by CTAs [16ch,16ch+16); the
// producer issues its bulk copy as soon as those 16 CTAs arrive (g_grp[ch]
// >= 16t). Compute warps stay fully decoupled via the full/empty rings.

#define BB   128
#define TT   256
#define HH   1024
#define CC   10
#define NCTA 128
#define NTHR 288        // 8 compute warps + 1 producer warp
#define NWC  8          // compute warps
#define JPC  8          // hidden units per CTA (32 gate rows)
#define KC   128        // K per staged chunk
#define NCH  8          // chunks per step
#define NBUF 3

// ---- SMEM layout (byte offsets from 128B-aligned base) ----
#define A_BASE  65536                   // W occupies [0, 65536)
#define A_BUF   32768                   // one buffer: 128 k-rows * 256B
#define MISC    (A_BASE + NBUF*A_BUF)   // 163840
#define SM_XW   (MISC)
#define SM_BS   (MISC + 128)
#define SM_FULL (MISC + 256)            // 3 x 8B full mbarriers
#define SM_EMPT (MISC + 256 + 24)       // 3 x 8B empty mbarriers
#define SM_EPI  (MISC + 256 + 48)       // 8B epi mbarrier
#define SMEM_DYN (MISC + 512)

typedef unsigned short ushort_t;

// h plane, k-major: byte(k,b) = k*256 + (((b>>3)^(k&7))<<4) + ((b&7)<<1)
__device__ __align__(128) __half g_hh[2][HH * BB];
__device__ unsigned g_grp[NCH];    // per-k-group arrival counters (16 CTAs each)

__global__ void reset_kernel() {
    if (threadIdx.x < NCH) g_grp[threadIdx.x] = 0u;
}

// ---------------- helpers ----------------
__device__ __forceinline__ uint32_t s2u(const void* p) {
    uint32_t a;
    asm("{ .reg .u64 t; cvta.to.shared.u64 t, %1; cvt.u32.u64 %0, t; }"
        : "=r"(a) : "l"(p));
    return a;
}

#define LDM4(r, addr) \
    asm volatile("ldmatrix.sync.aligned.m8n8.x4.shared.b16 {%0,%1,%2,%3}, [%4];" \
                 : "=r"((r)[0]), "=r"((r)[1]), "=r"((r)[2]), "=r"((r)[3]) \
                 : "r"(addr))

#define LDM4T(r, addr) \
    asm volatile("ldmatrix.sync.aligned.m8n8.x4.trans.shared.b16 {%0,%1,%2,%3}, [%4];" \
                 : "=r"((r)[0]), "=r"((r)[1]), "=r"((r)[2]), "=r"((r)[3]) \
                 : "r"(addr))

#define MMA(d, a, b0_, b1_) \
    asm volatile("mma.sync.aligned.m16n8k16.row.col.f32.f16.f16.f32 " \
                 "{%0,%1,%2,%3}, {%4,%5,%6,%7}, {%8,%9}, {%0,%1,%2,%3};" \
                 : "+f"((d)[0]), "+f"((d)[1]), "+f"((d)[2]), "+f"((d)[3]) \
                 : "r"((a)[0]), "r"((a)[1]), "r"((a)[2]), "r"((a)[3]), \
                   "r"(b0_), "r"(b1_))

__device__ __forceinline__ void mbar_init(uint32_t mbar, uint32_t cnt) {
    asm volatile("mbarrier.init.shared.b64 [%0], %1;" :: "r"(mbar), "r"(cnt) : "memory");
}
__device__ __forceinline__ void mbar_expect_tx(uint32_t mbar, uint32_t bytes) {
    asm volatile("mbarrier.arrive.expect_tx.shared.b64 _, [%0], %1;"
                 :: "r"(mbar), "r"(bytes) : "memory");
}
__device__ __forceinline__ void mbar_arrive(uint32_t mbar) {
    asm volatile("mbarrier.arrive.shared.b64 _, [%0];" :: "r"(mbar) : "memory");
}
__device__ __forceinline__ void bulk_g2s(uint32_t dst, const void* src,
                                         uint32_t bytes, uint32_t mbar) {
    asm volatile("cp.async.bulk.shared::cluster.global.mbarrier::complete_tx::bytes "
                 "[%0], [%1], %2, [%3];"
                 :: "r"(dst), "l"(src), "r"(bytes), "r"(mbar) : "memory");
}
__device__ __forceinline__ void mbar_wait(uint32_t mbar, uint32_t parity) {
    uint32_t done;
    asm volatile(
        "{\n\t.reg .pred p;\n\t"
        "mbarrier.try_wait.parity.acquire.cta.shared::cta.b64 p, [%1], %2;\n\t"
        "selp.b32 %0, 1, 0, p;\n\t}"
        : "=r"(done) : "r"(mbar), "r"(parity) : "memory");
    if (!done) {
        asm volatile(
            "{\n\t.reg .pred P1;\n\t"
            "WL_%=:\n\t"
            "mbarrier.try_wait.parity.acquire.cta.shared::cta.b64 P1, [%0], %1, 0x989680;\n\t"
            "@P1 bra.uni WD_%=;\n\t"
            "bra.uni WL_%=;\n\t"
            "WD_%=:\n\t}"
            :: "r"(mbar), "r"(parity) : "memory");
    }
}
__device__ __forceinline__ void fence_proxy_async_() {
    asm volatile("fence.proxy.async;" ::: "memory");
}
__device__ __forceinline__ ushort_t hfu(__half v) { return __half_as_ushort(v); }

// ---------------- main LSTM kernel ----------------
__global__ void __launch_bounds__(NTHR, 1) lstm_kernel(
    const float* __restrict__ x,
    const float* __restrict__ Wgx, const float* __restrict__ Wgh, const float* __restrict__ bg,
    const float* __restrict__ Wix, const float* __restrict__ Wih, const float* __restrict__ bi,
    const float* __restrict__ Wfx, const float* __restrict__ Wfh, const float* __restrict__ bf,
    const float* __restrict__ Wox, const float* __restrict__ Woh, const float* __restrict__ bo)
{
    extern __shared__ char smraw[];
    const uint32_t rawu = s2u(smraw);
    const uint32_t sb = (rawu + 127u) & ~127u;
    char* smem = smraw + (sb - rawu);

    const int tid  = threadIdx.x;
    const int lane = tid & 31;
    const int warp = tid >> 5;
    const int j0   = blockIdx.x * JPC;
    const int rot  = blockIdx.x & (NCH - 1);   // per-CTA chunk rotation

    // ---- one-time: W (fp16) -> SMEM ktile layout with (n&4) flip ----
    {
        const float* Wh[4] = {Wgh, Wih, Wfh, Woh};
        for (int idx = tid; idx < 32 * HH; idx += NTHR) {
            int n = idx >> 10, k = idx & (HH - 1);
            float w = Wh[n >> 3][(size_t)(j0 + (n & 7)) * HH + k];
            uint32_t off = (uint32_t)(k >> 4) * 1024u + (uint32_t)n * 32u
                         + (((uint32_t)(k & 15) * 2u) ^ (((uint32_t)n & 4u) << 2));
            *(ushort_t*)(smem + off) = hfu(__float2half(w));
        }
    }
    float* s_xw = (float*)(smem + SM_XW);
    float* s_bs = (float*)(smem + SM_BS);
    if (tid < 8) {
        s_xw[tid]      = Wgx[j0 + tid];  s_xw[8 + tid]  = Wix[j0 + tid];
        s_xw[16 + tid] = Wfx[j0 + tid];  s_xw[24 + tid] = Wox[j0 + tid];
        s_bs[tid]      = bg[j0 + tid];   s_bs[8 + tid]  = bi[j0 + tid];
        s_bs[16 + tid] = bf[j0 + tid];   s_bs[24 + tid] = bo[j0 + tid];
    }
    if (tid == 0) {
#pragma unroll
        for (int i = 0; i < NBUF; ++i) {
            mbar_init(sb + SM_FULL + (uint32_t)i * 8u, 1);
            mbar_init(sb + SM_EMPT + (uint32_t)i * 8u, NWC);
        }
        mbar_init(sb + SM_EPI, NWC);
    }
    __syncthreads();

    if (warp < NWC) {
        // ================= COMPUTE WARPS =================
        uint32_t aBase;
        {
            uint32_t kkb = (((uint32_t)lane & 16u) >> 1) + ((uint32_t)lane & 7u);
            uint32_t bgr = (uint32_t)warp * 2u + (((uint32_t)lane >> 3) & 1u);
            uint32_t sw  = (bgr ^ ((uint32_t)lane & 7u)) << 4;
            aBase = sb + A_BASE + kkb * 256u + sw;
        }
        uint32_t bAddr[2];
#pragma unroll
        for (int p = 0; p < 2; ++p) {
            int n = p * 16 + ((lane >> 4) << 3) + (lane & 7);
            bAddr[p] = sb + (uint32_t)n * 32
                     + (((uint32_t)((lane >> 3) & 1) * 16) ^ (((uint32_t)n & 4) << 2));
        }

        float cst[2][2];
#pragma unroll
        for (int rr = 0; rr < 2; ++rr) { cst[rr][0] = 0.0f; cst[rr][1] = 0.0f; }

        const int u0 = (lane & 3) * 2;
        int cs = 0; unsigned cph = 0;   // consumer ring cursor

        for (int t = 0; t < TT; ++t) {
            float D[4][4];
#pragma unroll
            for (int nt = 0; nt < 4; ++nt)
#pragma unroll
                for (int e = 0; e < 4; ++e) D[nt][e] = 0.0f;

            if (t > 0) {
                for (int i = 0; i < NCH; ++i) {
                    const int ch = (i + rot) & (NCH - 1);   // actual chunk
                    mbar_wait(sb + SM_FULL + (uint32_t)cs * 8u, cph);
                    const uint32_t boff = (uint32_t)cs * A_BUF;
#pragma unroll
                    for (int q = 0; q < 8; ++q) {
                        const uint32_t ao = aBase + boff + (uint32_t)q * 4096u;
                        const uint32_t wo = (uint32_t)(ch * 8 + q) * 1024u;
                        uint32_t ah[4];
                        uint32_t b0[4], b1[4];
                        LDM4T(ah, ao);
                        LDM4(b0, bAddr[0] + wo);
                        LDM4(b1, bAddr[1] + wo);
                        MMA(D[0], ah, b0[0], b0[1]);
                        MMA(D[1], ah, b0[2], b0[3]);
                        MMA(D[2], ah, b1[0], b1[1]);
                        MMA(D[3], ah, b1[2], b1[3]);
                    }
                    if (lane == 0) mbar_arrive(sb + SM_EMPT + (uint32_t)cs * 8u);
                    if (++cs == NBUF) { cs = 0; cph ^= 1; }
                }
            }

            // ---- epilogue: cell update fully in registers ----
            char* hdst = (char*)g_hh[t & 1];
#pragma unroll
            for (int rr = 0; rr < 2; ++rr) {
                const int b = warp * 16 + rr * 8 + (lane >> 2);
                const float xv = x[b * TT + t];
#pragma unroll
                for (int uu = 0; uu < 2; ++uu) {
                    const int u = u0 + uu;
                    const int e = rr * 2 + uu;
                    float zg = D[0][e] + xv * s_xw[u]      + s_bs[u];
                    float zi = D[1][e] + xv * s_xw[8 + u]  + s_bs[8 + u];
                    float zf = D[2][e] + xv * s_xw[16 + u] + s_bs[16 + u];
                    float zo = D[3][e] + xv * s_xw[24 + u] + s_bs[24 + u];
                    float gg = tanhf(zg);
                    float ii = 1.0f / (1.0f + __expf(-zi));
                    float ff = 1.0f / (1.0f + __expf(-zf));
                    float oo = 1.0f / (1.0f + __expf(-zo));
                    float c  = cst[rr][uu];
                    c = gg * ii + c * ff;
                    cst[rr][uu] = c;
                    float hn = tanhf(c) * oo;
                    const int kA = j0 + u;
                    const size_t off = (size_t)kA * 256
                                     + (size_t)((((unsigned)b >> 3) ^ ((unsigned)u & 7u)) << 4)
                                     + (size_t)(((unsigned)b & 7u) << 1);
                    *(ushort_t*)(hdst + off) = hfu(__float2half(hn));
                }
            }
            // signal: this warp's h stores issued
            __threadfence();
            if (lane == 0) mbar_arrive(sb + SM_EPI);
        }
    } else if (tid == NWC * 32) {
        // ================= PRODUCER THREAD =================
        int ps = 0; unsigned pph = 1;   // producer ring cursor (first waits pass)
        const int mygrp = blockIdx.x >> 4;   // this CTA's k-group (16 CTAs each)
        for (int t = 1; t < TT; ++t) {
            // wait for this CTA's step t-1 epilogue, then arrive on its group
            mbar_wait(sb + SM_EPI, (unsigned)(t - 1) & 1u);
            __threadfence();
            atomicAdd(&g_grp[mygrp], 1u);
            const char* hsrc = (const char*)g_hh[(t - 1) & 1];
            for (int i = 0; i < NCH; ++i) {
                const int ch = (i + rot) & (NCH - 1);   // rotated issue order
                // dataflow: wait only for chunk ch's 16 source CTAs
                volatile unsigned* gp = &g_grp[ch];
                const unsigned tgt = (unsigned)t * 16u;
                while (*gp < tgt) { __nanosleep(32); }
                __threadfence();
                fence_proxy_async_();
                mbar_wait(sb + SM_EMPT + (uint32_t)ps * 8u, pph);
                const uint32_t mb  = sb + SM_FULL + (uint32_t)ps * 8u;
                const uint32_t dst = sb + A_BASE + (uint32_t)ps * A_BUF;
                mbar_expect_tx(mb, A_BUF);
                bulk_g2s(dst, hsrc + (size_t)ch * A_BUF, A_BUF, mb);
                if (++ps == NBUF) { ps = 0; pph ^= 1; }
            }
        }
    }
}

// ---------------- projection ----------------
__global__ void proj_kernel(const float* __restrict__ Wp,
                            const float* __restrict__ bp,
                            float* __restrict__ out)
{
    __shared__ float red[256][CC];
    const int b = blockIdx.x;
    const int tid = threadIdx.x;
    const char* hs = (const char*)g_hh[(TT - 1) & 1];

    float p[CC];
#pragma unroll
    for (int c = 0; c < CC; ++c) p[c] = 0.0f;
    for (int k = tid; k < HH; k += 256) {
        const size_t off = (size_t)k * 256
                         + (size_t)((((unsigned)b >> 3) ^ ((unsigned)k & 7u)) << 4)
                         + (size_t)(((unsigned)b & 7u) << 1);
        float hv = __half2float(__ushort_as_half(*(const ushort_t*)(hs + off)));
#pragma unroll
        for (int c = 0; c < CC; ++c) p[c] += hv * Wp[k * CC + c];
    }
#pragma unroll
    for (int c = 0; c < CC; ++c) red[tid][c] = p[c];
    __syncthreads();
    if (tid < CC) {
        float s = 0.0f;
        for (int i = 0; i < 256; ++i) s += red[i][tid];
        out[b * CC + tid] = s + bp[tid];
    }
}

extern "C" void kernel_launch(void* const* d_in, const int* in_sizes, int n_in,
                              void* d_out, int out_size)
{
    (void)in_sizes; (void)n_in; (void)out_size;
    const float* x   = (const float*)d_in[0];
    const float* Wgx = (const float*)d_in[1];
    const float* Wgh = (const float*)d_in[2];
    const float* bg  = (const float*)d_in[3];
    const float* Wix = (const float*)d_in[4];
    const float* Wih = (const float*)d_in[5];
    const float* bi  = (const float*)d_in[6];
    const float* Wfx = (const float*)d_in[7];
    const float* Wfh = (const float*)d_in[8];
    const float* bf  = (const float*)d_in[9];
    const float* Wox = (const float*)d_in[10];
    const float* Woh = (const float*)d_in[11];
    const float* bo  = (const float*)d_in[12];
    const float* Wp  = (const float*)d_in[13];
    const float* bp  = (const float*)d_in[14];

    cudaFuncSetAttribute(lstm_kernel,
                         cudaFuncAttributeMaxDynamicSharedMemorySize, SMEM_DYN);

    reset_kernel<<<1, 32>>>();
    lstm_kernel<<<NCTA, NTHR, SMEM_DYN>>>(x, Wgx, Wgh, bg, Wix, Wih, bi,
                                          Wfx, Wfh, bf, Wox, Woh, bo);
    proj_kernel<<<BB, 256>>>(Wp, bp, (float*)d_out);
}

// round 16
// speedup vs baseline: 1.4125x; 1.4125x over previous
#include <cuda_runtime.h>
#include <cuda_fp16.h>
#include <stdint.h>

// LSTM B=128,T=256,H=1024,C=10 — persistent mma.sync kernel.
// R16 = R11 skeleton (single-pass fp16, warp-spec producer, monolithic
// barrier, NBUF=3) with BATCH-SPLIT ownership:
//   128 CTAs = 64 unit-groups x 2 batch-halves.
//   CTA (g,half): z for 16 units (n=64 gate rows) x 64 batches (M=64).
//   Per-CTA h read: 128 KB/step (was 256 KB) -> chip L2 16 MB/step.
// h stored as two contiguous half-planes [phase][half][k][64b], 128B/k-row.

#define BB   128
#define TT   256
#define HH   1024
#define CC   10
#define NCTA 128
#define NTHR 288        // 8 compute warps + 1 producer warp
#define NWC  8
#define KC   128        // K per staged chunk
#define NCH  8          // chunks per step
#define NBUF 3

// ---- SMEM layout (byte offsets from 128B-aligned base) ----
// W: 64 rows x 1024 k fp16, ktile-blocked (2048B per ktile) = 131072
#define A_BASE  131072
#define A_BUF   16384                   // one buffer: 128 k-rows * 128B
#define MISC    (A_BASE + NBUF*A_BUF)   // 180224
#define SM_XW   (MISC)                  // 64 floats
#define SM_BS   (MISC + 256)            // 64 floats
#define SM_FULL (MISC + 512)            // 3 x 8B
#define SM_EMPT (MISC + 512 + 24)       // 3 x 8B
#define SM_EPI  (MISC + 512 + 48)       // 8B
#define SMEM_DYN (MISC + 768)

typedef unsigned short ushort_t;

// h half-planes: byte(k, bl) = k*128 + (((bl>>3)^(k&7))<<4) + ((bl&7)<<1)
__device__ __align__(128) __half g_hh[2][2][HH * 64];   // [phase][half]
__device__ unsigned g_bar;

__global__ void reset_kernel() { g_bar = 0u; }

// ---------------- helpers ----------------
__device__ __forceinline__ uint32_t s2u(const void* p) {
    uint32_t a;
    asm("{ .reg .u64 t; cvta.to.shared.u64 t, %1; cvt.u32.u64 %0, t; }"
        : "=r"(a) : "l"(p));
    return a;
}

#define LDM4(r, addr) \
    asm volatile("ldmatrix.sync.aligned.m8n8.x4.shared.b16 {%0,%1,%2,%3}, [%4];" \
                 : "=r"((r)[0]), "=r"((r)[1]), "=r"((r)[2]), "=r"((r)[3]) \
                 : "r"(addr))

#define LDM4T(r, addr) \
    asm volatile("ldmatrix.sync.aligned.m8n8.x4.trans.shared.b16 {%0,%1,%2,%3}, [%4];" \
                 : "=r"((r)[0]), "=r"((r)[1]), "=r"((r)[2]), "=r"((r)[3]) \
                 : "r"(addr))

#define MMA(d, a, b0_, b1_) \
    asm volatile("mma.sync.aligned.m16n8k16.row.col.f32.f16.f16.f32 " \
                 "{%0,%1,%2,%3}, {%4,%5,%6,%7}, {%8,%9}, {%0,%1,%2,%3};" \
                 : "+f"((d)[0]), "+f"((d)[1]), "+f"((d)[2]), "+f"((d)[3]) \
                 : "r"((a)[0]), "r"((a)[1]), "r"((a)[2]), "r"((a)[3]), \
                   "r"(b0_), "r"(b1_))

__device__ __forceinline__ void mbar_init(uint32_t mbar, uint32_t cnt) {
    asm volatile("mbarrier.init.shared.b64 [%0], %1;" :: "r"(mbar), "r"(cnt) : "memory");
}
__device__ __forceinline__ void mbar_expect_tx(uint32_t mbar, uint32_t bytes) {
    asm volatile("mbarrier.arrive.expect_tx.shared.b64 _, [%0], %1;"
                 :: "r"(mbar), "r"(bytes) : "memory");
}
__device__ __forceinline__ void mbar_arrive(uint32_t mbar) {
    asm volatile("mbarrier.arrive.shared.b64 _, [%0];" :: "r"(mbar) : "memory");
}
__device__ __forceinline__ void bulk_g2s(uint32_t dst, const void* src,
                                         uint32_t bytes, uint32_t mbar) {
    asm volatile("cp.async.bulk.shared::cluster.global.mbarrier::complete_tx::bytes "
                 "[%0], [%1], %2, [%3];"
                 :: "r"(dst), "l"(src), "r"(bytes), "r"(mbar) : "memory");
}
__device__ __forceinline__ void mbar_wait(uint32_t mbar, uint32_t parity) {
    uint32_t done;
    asm volatile(
        "{\n\t.reg .pred p;\n\t"
        "mbarrier.try_wait.parity.acquire.cta.shared::cta.b64 p, [%1], %2;\n\t"
        "selp.b32 %0, 1, 0, p;\n\t}"
        : "=r"(done) : "r"(mbar), "r"(parity) : "memory");
    if (!done) {
        asm volatile(
            "{\n\t.reg .pred P1;\n\t"
            "WL_%=:\n\t"
            "mbarrier.try_wait.parity.acquire.cta.shared::cta.b64 P1, [%0], %1, 0x989680;\n\t"
            "@P1 bra.uni WD_%=;\n\t"
            "bra.uni WL_%=;\n\t"
            "WD_%=:\n\t}"
            :: "r"(mbar), "r"(parity) : "memory");
    }
}
__device__ __forceinline__ void fence_proxy_async_() {
    asm volatile("fence.proxy.async;" ::: "memory");
}
__device__ __forceinline__ ushort_t hfu(__half v) { return __half_as_ushort(v); }

// ---------------- main LSTM kernel ----------------
__global__ void __launch_bounds__(NTHR, 1) lstm_kernel(
    const float* __restrict__ x,
    const float* __restrict__ Wgx, const float* __restrict__ Wgh, const float* __restrict__ bg,
    const float* __restrict__ Wix, const float* __restrict__ Wih, const float* __restrict__ bi,
    const float* __restrict__ Wfx, const float* __restrict__ Wfh, const float* __restrict__ bf,
    const float* __restrict__ Wox, const float* __restrict__ Woh, const float* __restrict__ bo)
{
    extern __shared__ char smraw[];
    const uint32_t rawu = s2u(smraw);
    const uint32_t sb = (rawu + 127u) & ~127u;
    char* smem = smraw + (sb - rawu);

    const int tid  = threadIdx.x;
    const int lane = tid & 31;
    const int warp = tid >> 5;
    const int half = blockIdx.x & 1;         // batch half
    const int j0   = (blockIdx.x >> 1) * 16; // first unit of this group

    // ---- one-time: W (fp16) -> SMEM, 64 rows, ktile-blocked (2048B/ktile) ----
    // row n = nh*32 + gate*8 + jj  (nh picks units 8nh..8nh+8, jj unit-in-8)
    {
        const float* Wh[4] = {Wgh, Wih, Wfh, Woh};
        for (int idx = tid; idx < 64 * HH; idx += NTHR) {
            int n = idx >> 10, k = idx & (HH - 1);
            int nh = n >> 5, gate = (n >> 3) & 3, jj = n & 7;
            float w = Wh[gate][(size_t)(j0 + nh * 8 + jj) * HH + k];
            uint32_t off = (uint32_t)(k >> 4) * 2048u + (uint32_t)n * 32u
                         + (((uint32_t)(k & 15) * 2u) ^ (((uint32_t)n & 4u) << 2));
            *(ushort_t*)(smem + off) = hfu(__float2half(w));
        }
    }
    float* s_xw = (float*)(smem + SM_XW);
    float* s_bs = (float*)(smem + SM_BS);
    if (tid < 16) {
        s_xw[tid]      = Wgx[j0 + tid];  s_xw[16 + tid] = Wix[j0 + tid];
        s_xw[32 + tid] = Wfx[j0 + tid];  s_xw[48 + tid] = Wox[j0 + tid];
        s_bs[tid]      = bg[j0 + tid];   s_bs[16 + tid] = bi[j0 + tid];
        s_bs[32 + tid] = bf[j0 + tid];   s_bs[48 + tid] = bo[j0 + tid];
    }
    if (tid == 0) {
#pragma unroll
        for (int i = 0; i < NBUF; ++i) {
            mbar_init(sb + SM_FULL + (uint32_t)i * 8u, 1);
            mbar_init(sb + SM_EMPT + (uint32_t)i * 8u, NWC);
        }
        mbar_init(sb + SM_EPI, NWC);
    }
    __syncthreads();

    if (warp < NWC) {
        // ================= COMPUTE WARPS =================
        const int m  = warp & 3;     // M-tile (local batch rows m*16..)
        const int nh = warp >> 2;    // unit-half (n rows nh*32..)

        uint32_t aBase;
        {
            uint32_t kkb = (((uint32_t)lane & 16u) >> 1) + ((uint32_t)lane & 7u);
            uint32_t bgr = (uint32_t)m * 2u + (((uint32_t)lane >> 3) & 1u);   // 0..7
            uint32_t sw  = (bgr ^ ((uint32_t)lane & 7u)) << 4;
            aBase = sb + A_BASE + kkb * 128u + sw;
        }
        uint32_t bAddr[2];
#pragma unroll
        for (int p = 0; p < 2; ++p) {
            int n = nh * 32 + p * 16 + ((lane >> 4) << 3) + (lane & 7);
            bAddr[p] = sb + (uint32_t)n * 32
                     + (((uint32_t)((lane >> 3) & 1) * 16) ^ (((uint32_t)n & 4) << 2));
        }

        float cst[2][2];
#pragma unroll
        for (int rr = 0; rr < 2; ++rr) { cst[rr][0] = 0.0f; cst[rr][1] = 0.0f; }

        const int u0 = (lane & 3) * 2;
        int cs = 0; unsigned cph = 0;

        for (int t = 0; t < TT; ++t) {
            float D[4][4];
#pragma unroll
            for (int nt = 0; nt < 4; ++nt)
#pragma unroll
                for (int e = 0; e < 4; ++e) D[nt][e] = 0.0f;

            if (t > 0) {
                for (int ch = 0; ch < NCH; ++ch) {
                    mbar_wait(sb + SM_FULL + (uint32_t)cs * 8u, cph);
                    const uint32_t boff = (uint32_t)cs * A_BUF;
#pragma unroll
                    for (int q = 0; q < 8; ++q) {
                        const uint32_t ao = aBase + boff + (uint32_t)q * 2048u;
                        const uint32_t wo = (uint32_t)(ch * 8 + q) * 2048u;
                        uint32_t ah[4];
                        uint32_t b0[4], b1[4];
                        LDM4T(ah, ao);
                        LDM4(b0, bAddr[0] + wo);
                        LDM4(b1, bAddr[1] + wo);
                        MMA(D[0], ah, b0[0], b0[1]);
                        MMA(D[1], ah, b0[2], b0[3]);
                        MMA(D[2], ah, b1[0], b1[1]);
                        MMA(D[3], ah, b1[2], b1[3]);
                    }
                    if (lane == 0) mbar_arrive(sb + SM_EMPT + (uint32_t)cs * 8u);
                    if (++cs == NBUF) { cs = 0; cph ^= 1; }
                }
            }

            // ---- epilogue: cell update fully in registers ----
            char* hdst = (char*)g_hh[t & 1][half];
#pragma unroll
            for (int rr = 0; rr < 2; ++rr) {
                const int bl = m * 16 + rr * 8 + (lane >> 2);   // local batch 0..63
                const float xv = x[(half * 64 + bl) * TT + t];
#pragma unroll
                for (int uu = 0; uu < 2; ++uu) {
                    const int u  = u0 + uu;
                    const int ul = nh * 8 + u;                  // unit-in-16
                    const int e  = rr * 2 + uu;
                    float zg = D[0][e] + xv * s_xw[ul]      + s_bs[ul];
                    float zi = D[1][e] + xv * s_xw[16 + ul] + s_bs[16 + ul];
                    float zf = D[2][e] + xv * s_xw[32 + ul] + s_bs[32 + ul];
                    float zo = D[3][e] + xv * s_xw[48 + ul] + s_bs[48 + ul];
                    float gg = tanhf(zg);
                    float ii = 1.0f / (1.0f + __expf(-zi));
                    float ff = 1.0f / (1.0f + __expf(-zf));
                    float oo = 1.0f / (1.0f + __expf(-zo));
                    float c  = cst[rr][uu];
                    c = gg * ii + c * ff;
                    cst[rr][uu] = c;
                    float hn = tanhf(c) * oo;
                    const int kA = j0 + ul;                      // global unit
                    const size_t off = (size_t)kA * 128
                                     + (size_t)((((unsigned)bl >> 3) ^ ((unsigned)kA & 7u)) << 4)
                                     + (size_t)(((unsigned)bl & 7u) << 1);
                    *(ushort_t*)(hdst + off) = hfu(__float2half(hn));
                }
            }
            __threadfence();
            if (lane == 0) mbar_arrive(sb + SM_EPI);
        }
    } else if (tid == NWC * 32) {
        // ================= PRODUCER THREAD =================
        int ps = 0; unsigned pph = 1;
        for (int t = 1; t < TT; ++t) {
            mbar_wait(sb + SM_EPI, (unsigned)(t - 1) & 1u);
            __threadfence();
            atomicAdd(&g_bar, 1u);
            const unsigned tgt = (unsigned)t * NCTA;
            while (*(volatile unsigned*)&g_bar < tgt) { __nanosleep(32); }
            __threadfence();
            fence_proxy_async_();
            const char* hsrc = (const char*)g_hh[(t - 1) & 1][half];
            for (int ch = 0; ch < NCH; ++ch) {
                mbar_wait(sb + SM_EMPT + (uint32_t)ps * 8u, pph);
                const uint32_t mb  = sb + SM_FULL + (uint32_t)ps * 8u;
                const uint32_t dst = sb + A_BASE + (uint32_t)ps * A_BUF;
                mbar_expect_tx(mb, A_BUF);
                bulk_g2s(dst, hsrc + (size_t)ch * A_BUF, A_BUF, mb);
                if (++ps == NBUF) { ps = 0; pph ^= 1; }
            }
        }
    }
}

// ---------------- projection ----------------
__global__ void proj_kernel(const float* __restrict__ Wp,
                            const float* __restrict__ bp,
                            float* __restrict__ out)
{
    __shared__ float red[256][CC];
    const int b = blockIdx.x;
    const int tid = threadIdx.x;
    const int half = b >> 6;
    const int bl = b & 63;
    const char* hs = (const char*)g_hh[(TT - 1) & 1][half];

    float p[CC];
#pragma unroll
    for (int c = 0; c < CC; ++c) p[c] = 0.0f;
    for (int k = tid; k < HH; k += 256) {
        const size_t off = (size_t)k * 128
                         + (size_t)((((unsigned)bl >> 3) ^ ((unsigned)k & 7u)) << 4)
                         + (size_t)(((unsigned)bl & 7u) << 1);
        float hv = __half2float(__ushort_as_half(*(const ushort_t*)(hs + off)));
#pragma unroll
        for (int c = 0; c < CC; ++c) p[c] += hv * Wp[k * CC + c];
    }
#pragma unroll
    for (int c = 0; c < CC; ++c) red[tid][c] = p[c];
    __syncthreads();
    if (tid < CC) {
        float s = 0.0f;
        for (int i = 0; i < 256; ++i) s += red[i][tid];
        out[b * CC + tid] = s + bp[tid];
    }
}

extern "C" void kernel_launch(void* const* d_in, const int* in_sizes, int n_in,
                              void* d_out, int out_size)
{
    (void)in_sizes; (void)n_in; (void)out_size;
    const float* x   = (const float*)d_in[0];
    const float* Wgx = (const float*)d_in[1];
    const float* Wgh = (const float*)d_in[2];
    const float* bg  = (const float*)d_in[3];
    const float* Wix = (const float*)d_in[4];
    const float* Wih = (const float*)d_in[5];
    const float* bi  = (const float*)d_in[6];
    const float* Wfx = (const float*)d_in[7];
    const float* Wfh = (const float*)d_in[8];
    const float* bf  = (const float*)d_in[9];
    const float* Wox = (const float*)d_in[10];
    const float* Woh = (const float*)d_in[11];
    const float* bo  = (const float*)d_in[12];
    const float* Wp  = (const float*)d_in[13];
    const float* bp  = (const float*)d_in[14];

    cudaFuncSetAttribute(lstm_kernel,
                         cudaFuncAttributeMaxDynamicSharedMemorySize, SMEM_DYN);

    reset_kernel<<<1, 1>>>();
    lstm_kernel<<<NCTA, NTHR, SMEM_DYN>>>(x, Wgx, Wgh, bg, Wix, Wih, bi,
                                          Wfx, Wfh, bf, Wox, Woh, bo);
    proj_kernel<<<BB, 256>>>(Wp, bp, (float*)d_out);
}